// round 7
// baseline (speedup 1.0000x reference)
#include <cuda_runtime.h>
#include <cuda_fp16.h>

#define NN 200000
#define EE 6400000
#define HH 16
#define CC 40
#define NBIN 512
#define NG2 (NN / 16)              // 12500 groups of 16 nodes
#define NGB2 ((NG2 + 1023) / 1024) // 13
#define EIL_CAP 7000000

// ---------------- scratch (static device globals; no allocation) ----------------
__device__ int       g_cnt[NN];
__device__ int       g_scan[NN];
__device__ int       g_rowptr[NN + 1];
__device__ int       g_cursor[NN];
__device__ int       g_bsum[256];
__device__ int       g_boff[256];
__device__ float     g_dis[NN];
__device__ int       g_srcs[EE];
__device__ int       g_order[NN];
__device__ int       g_dbin[NBIN];
__device__ int       g_doff[NBIN];
__device__ int       g_dcur[NBIN];
// warp-interleaved ELL (x16)
__device__ int       g_eil[EIL_CAP];
__device__ int       g_gmax[NG2];
__device__ int       g_gscan[NG2];
__device__ int       g_gbsum[NGB2];
__device__ int       g_gboff[NGB2];
__device__ int       g_gbase[NG2 + 1];
// features fp16, PRE-SCALED by dis[node]; row NN is an always-zero pad row
__device__ __half    g_hA[(NN + 1) * HH];
__device__ __half    g_hB[(NN + 1) * HH];

// ---------------- CSR construction ----------------
__global__ void k_zero() {
    int i = blockIdx.x * 256 + threadIdx.x;
    if (i < NN) g_cnt[i] = 0;
    if (i < NBIN) { g_dbin[i] = 0; g_dcur[i] = 0; }
    if (i < 2) ((uint4*)g_hA)[NN * 2 + i] = make_uint4(0u, 0u, 0u, 0u);
    else if (i < 4) ((uint4*)g_hB)[NN * 2 + (i - 2)] = make_uint4(0u, 0u, 0u, 0u);
}

__global__ void k_hist(const int* __restrict__ ei) {
    int e = blockIdx.x * 256 + threadIdx.x;
    if (e < EE) atomicAdd(&g_cnt[ei[EE + e]], 1);
}

__global__ void k_scan1() {
    __shared__ int sh[1024];
    int t = threadIdx.x;
    int i = blockIdx.x * 1024 + t;
    int v = (i < NN) ? g_cnt[i] : 0;
    sh[t] = v;
    for (int off = 1; off < 1024; off <<= 1) {
        __syncthreads();
        int u = (t >= off) ? sh[t - off] : 0;
        __syncthreads();
        sh[t] += u;
    }
    __syncthreads();
    if (i < NN) g_scan[i] = sh[t];
    if (t == 1023) g_bsum[blockIdx.x] = sh[1023];
}

__global__ void k_scan2(int nb) {
    __shared__ int sh[256];
    int t = threadIdx.x;
    sh[t] = (t < nb) ? g_bsum[t] : 0;
    for (int off = 1; off < 256; off <<= 1) {
        __syncthreads();
        int u = (t >= off) ? sh[t - off] : 0;
        __syncthreads();
        sh[t] += u;
    }
    __syncthreads();
    if (t < nb) g_boff[t] = sh[t] - g_bsum[t];
}

__global__ void k_scan3() {
    int i = blockIdx.x * 256 + threadIdx.x;
    if (i < NN) {
        int ex = g_boff[i >> 10] + g_scan[i] - g_cnt[i];
        g_rowptr[i] = ex;
        g_cursor[i] = ex;
        g_dis[i] = rsqrtf((float)(g_cnt[i] + 1));
    }
    if (i == 0) g_rowptr[NN] = EE;
}

__global__ void k_scatter(const int* __restrict__ ei) {
    int e = blockIdx.x * 256 + threadIdx.x;
    if (e < EE) {
        int s = ei[e];
        int d = ei[EE + e];
        int p = atomicAdd(&g_cursor[d], 1);
        g_srcs[p] = s;
    }
}

// ---------------- degree counting sort ----------------
__global__ void k_dhist() {
    int i = blockIdx.x * 256 + threadIdx.x;
    if (i < NN) {
        int d = g_cnt[i]; if (d > NBIN - 1) d = NBIN - 1;
        atomicAdd(&g_dbin[d], 1);
    }
}

__global__ void k_dscan() {
    __shared__ int sh[NBIN];
    int t = threadIdx.x;
    sh[t] = g_dbin[t];
    for (int off = 1; off < NBIN; off <<= 1) {
        __syncthreads();
        int u = (t >= off) ? sh[t - off] : 0;
        __syncthreads();
        sh[t] += u;
    }
    __syncthreads();
    g_doff[t] = sh[t] - g_dbin[t];
}

__global__ void k_dplace() {
    int i = blockIdx.x * 256 + threadIdx.x;
    if (i < NN) {
        int d = g_cnt[i]; if (d > NBIN - 1) d = NBIN - 1;
        int p = g_doff[d] + atomicAdd(&g_dcur[d], 1);
        g_order[p] = i;
    }
}

// ---------------- warp-interleaved ELL (x16) build ----------------
__global__ void k_gmax() {
    int g = blockIdx.x * 256 + threadIdx.x;
    if (g < NG2) {
        int m = 0;
#pragma unroll
        for (int j = 0; j < 16; j++) {
            int d = g_cnt[g_order[g * 16 + j]];
            m = d > m ? d : m;
        }
        g_gmax[g] = m;
    }
}

__global__ void k_gscan1() {
    __shared__ int sh[1024];
    int t = threadIdx.x;
    int i = blockIdx.x * 1024 + t;
    int v = (i < NG2) ? g_gmax[i] : 0;
    sh[t] = v;
    for (int off = 1; off < 1024; off <<= 1) {
        __syncthreads();
        int u = (t >= off) ? sh[t - off] : 0;
        __syncthreads();
        sh[t] += u;
    }
    __syncthreads();
    if (i < NG2) g_gscan[i] = sh[t];
    if (t == 1023) g_gbsum[blockIdx.x] = sh[1023];
}

__global__ void k_gscan2() {
    if (threadIdx.x == 0) {
        int run = 0;
        for (int j = 0; j < NGB2; j++) { g_gboff[j] = run; run += g_gbsum[j]; }
    }
}

__global__ void k_gscan3() {
    int g = blockIdx.x * 256 + threadIdx.x;
    if (g < NG2) {
        int ex = g_gboff[g >> 10] + g_gscan[g] - g_gmax[g];
        g_gbase[g] = ex * 16;
    }
    if (g == 0) g_gbase[NG2] = (g_gboff[NGB2 - 1] + g_gbsum[NGB2 - 1]) * 16;
}

__global__ void k_fill() {  // one block per group: interleave x16 + pad with NN
    int g = blockIdx.x;
    int t = threadIdx.x;
    int base = g_gbase[g];
    int maxd = (g_gbase[g + 1] - base) >> 4;
    int j = t & 15;
    int node = g_order[g * 16 + j];
    int r = g_rowptr[node];
    int d = g_rowptr[node + 1] - r;
    for (int i = t >> 4; i < maxd; i += 16)
        g_eil[base + i * 16 + j] = (i < d) ? g_srcs[r + i] : NN;
}

// -------- first transform: store dis * (x @ w_in) --------
__global__ __launch_bounds__(256) void k_xw(const float* __restrict__ x,
                                            const float* __restrict__ w) {
    __shared__ float xs[16 * 128];
    __shared__ float ws[128 * 16];
    int t = threadIdx.x;
    for (int i = t; i < 2048; i += 256) ws[i] = w[i];
    const float* xb = x + (size_t)blockIdx.x * 2048;
    for (int i = t; i < 2048; i += 256) xs[i] = xb[i];
    __syncthreads();
    int ry = t >> 4, c = t & 15;
    float s = 0.f;
#pragma unroll
    for (int k = 0; k < 128; k++) s = fmaf(xs[ry * 128 + k], ws[k * 16 + c], s);
    int node = blockIdx.x * 16 + ry;
    g_hA[(size_t)node * 16 + c] = __float2half_rn(s * g_dis[node]);
}

// ---------------- fused aggregation layers ----------------
// 2 lanes per node; each lane owns 8 dims (one 16B LDG.128). Warp = 16 nodes,
// 16 edges in flight per gather instruction (2x MLP vs 4-lane layout).
__device__ __forceinline__ void h8_init(float* a, uint4 v) {
    __half2* h = (__half2*)&v;
#pragma unroll
    for (int q = 0; q < 4; q++) {
        float2 f = __half22float2(h[q]);
        a[2 * q] = f.x; a[2 * q + 1] = f.y;
    }
}
__device__ __forceinline__ void h8_add(float* a, uint4 v) {
    __half2* h = (__half2*)&v;
#pragma unroll
    for (int q = 0; q < 4; q++) {
        float2 f = __half22float2(h[q]);
        a[2 * q] += f.x; a[2 * q + 1] += f.y;
    }
}
__device__ __forceinline__ uint4 f8_to_h8(const float* a) {
    uint4 r;
    __half2* h = (__half2*)&r;
#pragma unroll
    for (int q = 0; q < 4; q++) h[q] = __floats2half2_rn(a[2 * q], a[2 * q + 1]);
    return r;
}

// MODE 0: h = relu(dis*agg+b); store dis*(h @ Wn)               [used 8x]
// MODE 1: store dis*relu(dis*agg+b)                              [produces h9-hat]
// MODE 2: o = (dis*agg) @ w_out + b_out; out = log_softmax(o)    [final]
template <int MODE>
__global__ __launch_bounds__(256) void k_agg(int inA,
                                             const float* __restrict__ preBias,
                                             const float* __restrict__ Wn,
                                             const float* __restrict__ postBias,
                                             float* __restrict__ fout) {
    __shared__ float wsh[640];
    __shared__ float bsh[40];
    __shared__ float hsh[128 * 17];
    int t = threadIdx.x;
    if (MODE == 0) {
        wsh[t] = Wn[t & 255];
    }
    if (MODE == 2) {
        for (int i = t; i < 640; i += 256) wsh[i] = Wn[i];
        if (t < 40) bsh[t] = postBias[t];
    }
    __syncthreads();

    int gw = blockIdx.x * 8 + (t >> 5);   // group id == global warp id
    if (gw >= NG2) return;

    const __half* inF = inA ? g_hA : g_hB;
    __half* outF = inA ? g_hB : g_hA;
    const uint4* in4 = (const uint4*)inF;

    int lane = t & 31;
    int j = lane >> 1;                     // node slot 0..15
    int sub = lane & 1;                    // half-feature owner
    int node = g_order[gw * 16 + j];
    float di = g_dis[node];

    float acc[8];
    h8_init(acc, __ldg(&in4[node * 2 + sub]));   // self loop
    int base = g_gbase[gw];
    int maxd = (g_gbase[gw + 1] - base) >> 4;
    const int* ep = g_eil + base + j;
#pragma unroll 4
    for (int i = 0; i < maxd; i++) {
        int s = __ldg(ep + i * 16);        // 64B coalesced per warp
        h8_add(acc, __ldg(&in4[s * 2 + sub]));
    }
#pragma unroll
    for (int q = 0; q < 8; q++) acc[q] *= di;

    if (MODE != 2) {  // bias + relu
        const float* bp = preBias + sub * 8;
#pragma unroll
        for (int q = 0; q < 8; q++) acc[q] = fmaxf(acc[q] + __ldg(bp + q), 0.f);
    }

    if (MODE == 1) {  // store dis*h for next layer
#pragma unroll
        for (int q = 0; q < 8; q++) acc[q] *= di;
        ((uint4*)outF)[node * 2 + sub] = f8_to_h8(acc);
        return;
    }

    // share the node's 16-vector between its 2 lanes
    float* hr = &hsh[(t >> 1) * 17];
#pragma unroll
    for (int q = 0; q < 8; q++) hr[sub * 8 + q] = acc[q];
    __syncwarp();

    if (MODE == 0) {  // 16x16 transform, store pre-scaled by dis
        float o[8];
#pragma unroll
        for (int jj = 0; jj < 8; jj++) {
            int col = sub * 8 + jj;
            float s = 0.f;
#pragma unroll
            for (int k = 0; k < 16; k++) s = fmaf(hr[k], wsh[k * 16 + col], s);
            o[jj] = s * di;
        }
        ((uint4*)outF)[node * 2 + sub] = f8_to_h8(o);
    } else {  // MODE 2: 16x40 output transform + log_softmax
        float o[20];
#pragma unroll
        for (int jj = 0; jj < 20; jj++) {
            int col = sub * 20 + jj;
            float s = bsh[col];
#pragma unroll
            for (int k = 0; k < 16; k++) s = fmaf(hr[k], wsh[k * 40 + col], s);
            o[jj] = s;
        }
        float m = o[0];
#pragma unroll
        for (int jj = 1; jj < 20; jj++) m = fmaxf(m, o[jj]);
        m = fmaxf(m, __shfl_xor_sync(0xffffffffu, m, 1));
        float se = 0.f;
#pragma unroll
        for (int jj = 0; jj < 20; jj++) se += __expf(o[jj] - m);
        se += __shfl_xor_sync(0xffffffffu, se, 1);
        float l = m + __logf(se);
#pragma unroll
        for (int jj = 0; jj < 20; jj++)
            fout[(size_t)node * 40 + sub * 20 + jj] = o[jj] - l;
    }
}

// ---------------- launch ----------------
extern "C" void kernel_launch(void* const* d_in, const int* in_sizes, int n_in,
                              void* d_out, int out_size) {
    const float* x     = (const float*)d_in[0];
    const float* w_in  = (const float*)d_in[1];
    const float* b_in  = (const float*)d_in[2];
    const float* w_hid = (const float*)d_in[3];
    const float* b_hid = (const float*)d_in[4];
    const float* w_out = (const float*)d_in[5];
    const float* b_out = (const float*)d_in[6];
    const int*   ei    = (const int*)d_in[7];
    float* out = (float*)d_out;

    const int NB_N = (NN + 255) / 256;    // 782
    const int NB_E = EE / 256;            // 25000
    const int NB_S = (NN + 1023) / 1024;  // 196
    const int NB_G = (NG2 + 255) / 256;   // 49
    const int NB_A = (NG2 + 7) / 8;       // 1563

    // CSR build
    k_zero<<<NB_N, 256>>>();
    k_hist<<<NB_E, 256>>>(ei);
    k_scan1<<<NB_S, 1024>>>();
    k_scan2<<<1, 256>>>(NB_S);
    k_scan3<<<NB_N, 256>>>();
    k_scatter<<<NB_E, 256>>>(ei);

    // degree counting sort
    k_dhist<<<NB_N, 256>>>();
    k_dscan<<<1, NBIN>>>();
    k_dplace<<<NB_N, 256>>>();

    // warp-interleaved ELL (x16)
    k_gmax<<<NB_G, 256>>>();
    k_gscan1<<<NGB2, 1024>>>();
    k_gscan2<<<1, 32>>>();
    k_gscan3<<<NB_G, 256>>>();
    k_fill<<<NG2, 256>>>();

    // t0-hat = dis * (x @ w_in)  -> g_hA
    k_xw<<<NN / 16, 256>>>(x, w_in);

    // layers 1..8: fused agg + bias + relu + next 16x16 transform (ping-pong)
    k_agg<0><<<NB_A, 256>>>(1, b_in,         w_hid + 0 * 256, nullptr, nullptr);
    k_agg<0><<<NB_A, 256>>>(0, b_hid + 0*16, w_hid + 1 * 256, nullptr, nullptr);
    k_agg<0><<<NB_A, 256>>>(1, b_hid + 1*16, w_hid + 2 * 256, nullptr, nullptr);
    k_agg<0><<<NB_A, 256>>>(0, b_hid + 2*16, w_hid + 3 * 256, nullptr, nullptr);
    k_agg<0><<<NB_A, 256>>>(1, b_hid + 3*16, w_hid + 4 * 256, nullptr, nullptr);
    k_agg<0><<<NB_A, 256>>>(0, b_hid + 4*16, w_hid + 5 * 256, nullptr, nullptr);
    k_agg<0><<<NB_A, 256>>>(1, b_hid + 5*16, w_hid + 6 * 256, nullptr, nullptr);
    k_agg<0><<<NB_A, 256>>>(0, b_hid + 6*16, w_hid + 7 * 256, nullptr, nullptr);
    // layer 9: h9-hat = dis*relu(dis*agg(t8) + b_hid[7])   (hA -> hB)
    k_agg<1><<<NB_A, 256>>>(1, b_hid + 7*16, nullptr, nullptr, nullptr);
    // layer 10: out = log_softmax((dis*agg(h9-hat)) @ w_out + b_out)
    k_agg<2><<<NB_A, 256>>>(0, nullptr, w_out, b_out, out);
}

// round 8
// speedup vs baseline: 1.0648x; 1.0648x over previous
#include <cuda_runtime.h>
#include <cuda_fp16.h>

#define NN 200000
#define EE 6400000
#define HH 16
#define CC 40
#define NBIN 512
#define ILV 16                      // ELL interleave: 16 nodes per warp-group
#define NG2 (NN / ILV)              // 12500 groups
#define NGB2 ((NG2 + 1023) / 1024)  // 13
#define EIL_CAP 7000000
#define DEPTH 4                     // cp.async pipeline depth

// ---------------- scratch (static device globals; no allocation) ----------------
__device__ int    g_cnt[NN];
__device__ float  g_dis[NN];        // node order (for k_xw)
__device__ float  g_disP[NN];       // rank order (for k_agg)
__device__ int    g_order[NN];      // rank -> node
__device__ int    g_rank[NN];       // node -> rank
__device__ int2   g_sbc[NN];        // .x cursor (atomic), .y slotbase (gbase + j)
__device__ int    g_dbin[NBIN];
__device__ int    g_doff[NBIN];
__device__ int    g_dcur[NBIN];
__device__ int    g_eil[EIL_CAP];   // x16-interleaved ELL, entries are RANKS
__device__ int    g_gmax[NG2];
__device__ int    g_gscan[NG2];
__device__ int    g_gbsum[NGB2];
__device__ int    g_gboff[NGB2];
__device__ int    g_gbase[NG2 + 1]; // slot base per group (int units)
// features fp16, RANK order, PRE-SCALED by dis; row NN is an always-zero pad row
__device__ __half g_hA[(NN + 1) * HH];
__device__ __half g_hB[(NN + 1) * HH];

// ---------------- prep ----------------
__global__ void k_zero() {
    int i = blockIdx.x * 256 + threadIdx.x;
    if (i < NN) { g_cnt[i] = 0; g_sbc[i].x = 0; }
    if (i < NBIN) { g_dbin[i] = 0; g_dcur[i] = 0; }
    if (i < 2) ((uint4*)g_hA)[NN * 2 + i] = make_uint4(0u, 0u, 0u, 0u);
    else if (i < 4) ((uint4*)g_hB)[NN * 2 + (i - 2)] = make_uint4(0u, 0u, 0u, 0u);
}

__global__ void k_hist(const int* __restrict__ ei) {
    int e = blockIdx.x * 256 + threadIdx.x;
    if (e < EE) atomicAdd(&g_cnt[ei[EE + e]], 1);
}

__global__ void k_dhist() {  // degree histogram + dis (fused)
    int i = blockIdx.x * 256 + threadIdx.x;
    if (i < NN) {
        int d = g_cnt[i];
        g_dis[i] = rsqrtf((float)(d + 1));
        if (d > NBIN - 1) d = NBIN - 1;
        atomicAdd(&g_dbin[d], 1);
    }
}

__global__ void k_dscan() {
    __shared__ int sh[NBIN];
    int t = threadIdx.x;
    sh[t] = g_dbin[t];
    for (int off = 1; off < NBIN; off <<= 1) {
        __syncthreads();
        int u = (t >= off) ? sh[t - off] : 0;
        __syncthreads();
        sh[t] += u;
    }
    __syncthreads();
    g_doff[t] = sh[t] - g_dbin[t];
}

__global__ void k_dplace() {
    int i = blockIdx.x * 256 + threadIdx.x;
    if (i < NN) {
        int d = g_cnt[i]; if (d > NBIN - 1) d = NBIN - 1;
        int p = g_doff[d] + atomicAdd(&g_dcur[d], 1);
        g_order[p] = i;
        g_rank[i] = p;
        g_disP[p] = g_dis[i];
    }
}

__global__ void k_gmax() {
    int g = blockIdx.x * 256 + threadIdx.x;
    if (g < NG2) {
        int m = 0;
#pragma unroll
        for (int j = 0; j < ILV; j++) {
            int d = g_cnt[g_order[g * ILV + j]];
            m = d > m ? d : m;
        }
        g_gmax[g] = m;
    }
}

__global__ void k_gscan1() {
    __shared__ int sh[1024];
    int t = threadIdx.x;
    int i = blockIdx.x * 1024 + t;
    int v = (i < NG2) ? g_gmax[i] : 0;
    sh[t] = v;
    for (int off = 1; off < 1024; off <<= 1) {
        __syncthreads();
        int u = (t >= off) ? sh[t - off] : 0;
        __syncthreads();
        sh[t] += u;
    }
    __syncthreads();
    if (i < NG2) g_gscan[i] = sh[t];
    if (t == 1023) g_gbsum[blockIdx.x] = sh[1023];
}

__global__ void k_gscan2() {
    if (threadIdx.x == 0) {
        int run = 0;
        for (int j = 0; j < NGB2; j++) { g_gboff[j] = run; run += g_gbsum[j]; }
    }
}

__global__ void k_gscan3() {
    int g = blockIdx.x * 256 + threadIdx.x;
    if (g < NG2) {
        int ex = g_gboff[g >> 10] + g_gscan[g] - g_gmax[g];
        g_gbase[g] = ex * ILV;
    }
    if (g == 0) g_gbase[NG2] = (g_gboff[NGB2 - 1] + g_gbsum[NGB2 - 1]) * ILV;
}

__global__ void k_sb() {  // per-node slot base = gbase[group(rank)] + lane(rank)
    int i = blockIdx.x * 256 + threadIdx.x;
    if (i < NN) {
        int r = g_rank[i];
        g_sbc[i].y = g_gbase[r >> 4] + (r & 15);
    }
}

__global__ void k_pad() {  // fill ALL ELL slots with pad rank NN
    int i = blockIdx.x * 256 + threadIdx.x;
    if (i < EIL_CAP) g_eil[i] = NN;
}

__global__ void k_scatter2(const int* __restrict__ ei) {
    int e = blockIdx.x * 256 + threadIdx.x;
    if (e < EE) {
        int s = ei[e];
        int d = ei[EE + e];
        int i = atomicAdd(&g_sbc[d].x, 1);
        int sb = g_sbc[d].y;                 // same 8B pair as cursor
        g_eil[sb + i * ILV] = g_rank[s];     // store src RANK
    }
}

// -------- first transform: g_hA[rank(n)] = dis[n] * (x[n] @ w_in) --------
__global__ __launch_bounds__(256) void k_xw(const float* __restrict__ x,
                                            const float* __restrict__ w) {
    __shared__ float xs[16 * 128];
    __shared__ float ws[128 * 16];
    int t = threadIdx.x;
    for (int i = t; i < 2048; i += 256) ws[i] = w[i];
    const float* xb = x + (size_t)blockIdx.x * 2048;
    for (int i = t; i < 2048; i += 256) xs[i] = xb[i];
    __syncthreads();
    int ry = t >> 4, c = t & 15;
    float s = 0.f;
#pragma unroll
    for (int k = 0; k < 128; k++) s = fmaf(xs[ry * 128 + k], ws[k * 16 + c], s);
    int node = blockIdx.x * 16 + ry;
    g_hA[(size_t)g_rank[node] * 16 + c] = __float2half_rn(s * g_dis[node]);
}

// ---------------- cp.async helpers ----------------
__device__ __forceinline__ void cp16(unsigned smem, const void* gptr) {
    asm volatile("cp.async.cg.shared.global [%0], [%1], 16;"
                 :: "r"(smem), "l"(gptr) : "memory");
}
__device__ __forceinline__ void cp_commit() {
    asm volatile("cp.async.commit_group;" ::: "memory");
}
template <int N>
__device__ __forceinline__ void cp_wait() {
    asm volatile("cp.async.wait_group %0;" :: "n"(N) : "memory");
}

__device__ __forceinline__ void h8_init(float* a, uint4 v) {
    __half2* h = (__half2*)&v;
#pragma unroll
    for (int q = 0; q < 4; q++) {
        float2 f = __half22float2(h[q]);
        a[2 * q] = f.x; a[2 * q + 1] = f.y;
    }
}
__device__ __forceinline__ void h8_add(float* a, uint4 v) {
    __half2* h = (__half2*)&v;
#pragma unroll
    for (int q = 0; q < 4; q++) {
        float2 f = __half22float2(h[q]);
        a[2 * q] += f.x; a[2 * q + 1] += f.y;
    }
}
__device__ __forceinline__ uint4 f8_to_h8(const float* a) {
    uint4 r;
    __half2* h = (__half2*)&r;
#pragma unroll
    for (int q = 0; q < 4; q++) h[q] = __floats2half2_rn(a[2 * q], a[2 * q + 1]);
    return r;
}

// ---------------- fused aggregation layers (cp.async gather pipeline) -------
// Warp = 16 nodes (ranks gw*16..+15), 2 lanes/node, each lane owns 16B of the
// 32B fp16 row. Chunk c = the c-th ELL edge of each of the 16 nodes: one
// 64B-coalesced index load + one LDGSTS staging 32x16B, consumed privately.
//
// MODE 0: h = relu(dis*agg+b); store dis*(h @ Wn)    [8x]
// MODE 1: store dis*relu(dis*agg+b)                   [h9]
// MODE 2: o = (dis*agg) @ w_out + b_out; log_softmax  [final]
template <int MODE>
__global__ __launch_bounds__(256) void k_agg(int inA,
                                             const float* __restrict__ preBias,
                                             const float* __restrict__ Wn,
                                             const float* __restrict__ postBias,
                                             float* __restrict__ fout) {
    __shared__ uint4 stage[8][DEPTH][32];
    __shared__ float wsh[640];
    __shared__ float bsh[40];
    __shared__ float hsh[128 * 17];
    int t = threadIdx.x;
    if (MODE == 0) wsh[t] = Wn[t & 255];
    if (MODE == 2) {
        for (int i = t; i < 640; i += 256) wsh[i] = Wn[i];
        if (t < 40) bsh[t] = postBias[t];
    }
    __syncthreads();

    int w = t >> 5, lane = t & 31;
    int gw = blockIdx.x * 8 + w;
    if (gw >= NG2) return;

    const uint4* tab = (const uint4*)(inA ? g_hA : g_hB);
    __half* outF = inA ? g_hB : g_hA;

    int j = lane >> 1, h = lane & 1;
    int row = gw * ILV + j;            // rank-ordered feature row
    float di = g_disP[row];

    float acc[8];
    h8_init(acc, __ldg(&tab[row * 2 + h]));   // self loop (coalesced)

    int base = g_gbase[gw];
    int nch = (g_gbase[gw + 1] - base) >> 4;
    const int* eilc = g_eil + base + j;
    unsigned sa0 = (unsigned)__cvta_generic_to_shared(&stage[w][0][lane]);

    int npro = nch < DEPTH ? nch : DEPTH;
    for (int c = 0; c < npro; c++) {
        int src = __ldg(eilc + c * ILV);
        cp16(sa0 + (c & (DEPTH - 1)) * 512, tab + src * 2 + h);
        cp_commit();
    }
    int c = 0;
    for (; c + DEPTH < nch; c++) {
        cp_wait<DEPTH - 1>();                       // buf c ready
        h8_add(acc, stage[w][c & (DEPTH - 1)][lane]);
        int cn = c + DEPTH;
        int src = __ldg(eilc + cn * ILV);
        cp16(sa0 + (cn & (DEPTH - 1)) * 512, tab + src * 2 + h);
        cp_commit();
    }
    cp_wait<0>();
    for (; c < nch; c++) h8_add(acc, stage[w][c & (DEPTH - 1)][lane]);

#pragma unroll
    for (int q = 0; q < 8; q++) acc[q] *= di;

    if (MODE != 2) {  // bias + relu
        const float* bp = preBias + h * 8;
#pragma unroll
        for (int q = 0; q < 8; q++) acc[q] = fmaxf(acc[q] + __ldg(bp + q), 0.f);
    }

    if (MODE == 1) {  // store dis*h (coalesced, rank order)
#pragma unroll
        for (int q = 0; q < 8; q++) acc[q] *= di;
        ((uint4*)outF)[row * 2 + h] = f8_to_h8(acc);
        return;
    }

    // share the node's 16-vector between its 2 lanes
    float* hr = &hsh[(t >> 1) * 17];
#pragma unroll
    for (int q = 0; q < 8; q++) hr[h * 8 + q] = acc[q];
    __syncwarp();

    if (MODE == 0) {  // 16x16 transform, store pre-scaled by dis
        float o[8];
#pragma unroll
        for (int jj = 0; jj < 8; jj++) {
            int col = h * 8 + jj;
            float s = 0.f;
#pragma unroll
            for (int k = 0; k < 16; k++) s = fmaf(hr[k], wsh[k * 16 + col], s);
            o[jj] = s * di;
        }
        ((uint4*)outF)[row * 2 + h] = f8_to_h8(o);
    } else {  // MODE 2: 16x40 output transform + log_softmax
        float o[20];
#pragma unroll
        for (int jj = 0; jj < 20; jj++) {
            int col = h * 20 + jj;
            float s = bsh[col];
#pragma unroll
            for (int k = 0; k < 16; k++) s = fmaf(hr[k], wsh[k * 40 + col], s);
            o[jj] = s;
        }
        float m = o[0];
#pragma unroll
        for (int jj = 1; jj < 20; jj++) m = fmaxf(m, o[jj]);
        m = fmaxf(m, __shfl_xor_sync(0xffffffffu, m, 1));
        float se = 0.f;
#pragma unroll
        for (int jj = 0; jj < 20; jj++) se += __expf(o[jj] - m);
        se += __shfl_xor_sync(0xffffffffu, se, 1);
        float l = m + __logf(se);
        int node = g_order[row];
#pragma unroll
        for (int jj = 0; jj < 20; jj++)
            fout[(size_t)node * 40 + h * 20 + jj] = o[jj] - l;
    }
}

// ---------------- launch ----------------
extern "C" void kernel_launch(void* const* d_in, const int* in_sizes, int n_in,
                              void* d_out, int out_size) {
    const float* x     = (const float*)d_in[0];
    const float* w_in  = (const float*)d_in[1];
    const float* b_in  = (const float*)d_in[2];
    const float* w_hid = (const float*)d_in[3];
    const float* b_hid = (const float*)d_in[4];
    const float* w_out = (const float*)d_in[5];
    const float* b_out = (const float*)d_in[6];
    const int*   ei    = (const int*)d_in[7];
    float* out = (float*)d_out;

    const int NB_N = (NN + 255) / 256;    // 782
    const int NB_E = EE / 256;            // 25000
    const int NB_G = (NG2 + 255) / 256;   // 49
    const int NB_A = (NG2 + 7) / 8;       // 1563
    const int NB_P = (EIL_CAP + 255) / 256;

    // prep: counts -> degree sort -> group bases -> direct ELL scatter
    k_zero<<<NB_N, 256>>>();
    k_hist<<<NB_E, 256>>>(ei);
    k_dhist<<<NB_N, 256>>>();
    k_dscan<<<1, NBIN>>>();
    k_dplace<<<NB_N, 256>>>();
    k_gmax<<<NB_G, 256>>>();
    k_gscan1<<<NGB2, 1024>>>();
    k_gscan2<<<1, 32>>>();
    k_gscan3<<<NB_G, 256>>>();
    k_sb<<<NB_N, 256>>>();
    k_pad<<<NB_P, 256>>>();
    k_scatter2<<<NB_E, 256>>>(ei);

    // t0-hat = dis * (x @ w_in)  -> g_hA (rank order)
    k_xw<<<NN / 16, 256>>>(x, w_in);

    // layers 1..8: fused agg + bias + relu + next 16x16 transform (ping-pong)
    k_agg<0><<<NB_A, 256>>>(1, b_in,         w_hid + 0 * 256, nullptr, nullptr);
    k_agg<0><<<NB_A, 256>>>(0, b_hid + 0*16, w_hid + 1 * 256, nullptr, nullptr);
    k_agg<0><<<NB_A, 256>>>(1, b_hid + 1*16, w_hid + 2 * 256, nullptr, nullptr);
    k_agg<0><<<NB_A, 256>>>(0, b_hid + 2*16, w_hid + 3 * 256, nullptr, nullptr);
    k_agg<0><<<NB_A, 256>>>(1, b_hid + 3*16, w_hid + 4 * 256, nullptr, nullptr);
    k_agg<0><<<NB_A, 256>>>(0, b_hid + 4*16, w_hid + 5 * 256, nullptr, nullptr);
    k_agg<0><<<NB_A, 256>>>(1, b_hid + 5*16, w_hid + 6 * 256, nullptr, nullptr);
    k_agg<0><<<NB_A, 256>>>(0, b_hid + 6*16, w_hid + 7 * 256, nullptr, nullptr);
    // layer 9: h9-hat (hA -> hB)
    k_agg<1><<<NB_A, 256>>>(1, b_hid + 7*16, nullptr, nullptr, nullptr);
    // layer 10: out = log_softmax((dis*agg(h9-hat)) @ w_out + b_out)
    k_agg<2><<<NB_A, 256>>>(0, nullptr, w_out, b_out, out);
}

// round 9
// speedup vs baseline: 1.0805x; 1.0148x over previous
#include <cuda_runtime.h>
#include <cuda_fp16.h>

#define NN 200000
#define EE 6400000
#define HH 16
#define CC 40
#define NBIN 512
#define ILV 16                      // ELL interleave: 16 nodes per warp-group
#define NG2 (NN / ILV)              // 12500 groups
#define NGB2 ((NG2 + 1023) / 1024)  // 13
#define EIL_CAP 7000000
#define DEPTH 4                     // cp.async pipeline depth

// ---------------- scratch (static device globals; no allocation) ----------------
__device__ int    g_cnt[NN];
__device__ float  g_dis[NN];        // node order (for k_xw)
__device__ float  g_disP[NN];       // rank order (for k_agg)
__device__ int    g_order[NN];      // rank -> node
__device__ int    g_rank[NN];       // node -> rank
__device__ int2   g_sbc[NN];        // .x cursor (atomic), .y slotbase
__device__ int    g_dbin[NBIN];
__device__ int    g_doff[NBIN];
__device__ int    g_dcur[NBIN];
__device__ int    g_eil[EIL_CAP];   // x16-interleaved ELL, entries are RANKS
__device__ int    g_gmax[NG2];
__device__ int    g_gscan[NG2];
__device__ int    g_gbsum[NGB2];
__device__ int    g_gbase[NG2 + 1]; // slot base per group (int units)
// features fp16, RANK order, PRE-SCALED by dis; row NN is an always-zero pad row
__device__ __half g_hA[(NN + 1) * HH];
__device__ __half g_hB[(NN + 1) * HH];

// ---------------- prep ----------------
__global__ void k_zero() {
    int i = blockIdx.x * 256 + threadIdx.x;
    if (i < NN) { g_cnt[i] = 0; g_sbc[i].x = 0; }
    if (i < NBIN) { g_dbin[i] = 0; g_dcur[i] = 0; }
    if (i < 2) ((uint4*)g_hA)[NN * 2 + i] = make_uint4(0u, 0u, 0u, 0u);
    else if (i < 4) ((uint4*)g_hB)[NN * 2 + (i - 2)] = make_uint4(0u, 0u, 0u, 0u);
}

__global__ void k_hist(const int* __restrict__ ei) {
    int e = blockIdx.x * 256 + threadIdx.x;
    if (e < EE) atomicAdd(&g_cnt[ei[EE + e]], 1);
}

__global__ void k_dhist() {  // degree histogram + dis (fused)
    int i = blockIdx.x * 256 + threadIdx.x;
    if (i < NN) {
        int d = g_cnt[i];
        g_dis[i] = rsqrtf((float)(d + 1));
        if (d > NBIN - 1) d = NBIN - 1;
        atomicAdd(&g_dbin[d], 1);
    }
}

__global__ void k_dscan() {
    __shared__ int sh[NBIN];
    int t = threadIdx.x;
    sh[t] = g_dbin[t];
    for (int off = 1; off < NBIN; off <<= 1) {
        __syncthreads();
        int u = (t >= off) ? sh[t - off] : 0;
        __syncthreads();
        sh[t] += u;
    }
    __syncthreads();
    g_doff[t] = sh[t] - g_dbin[t];
}

__global__ void k_dplace() {
    int i = blockIdx.x * 256 + threadIdx.x;
    if (i < NN) {
        int d = g_cnt[i]; if (d > NBIN - 1) d = NBIN - 1;
        int p = g_doff[d] + atomicAdd(&g_dcur[d], 1);
        g_order[p] = i;
        g_rank[i] = p;
        g_disP[p] = g_dis[i];
    }
}

// fused: per-group max degree + 1024-wide inclusive scan of maxes
__global__ void k_gmaxscan() {
    __shared__ int sh[1024];
    int t = threadIdx.x;
    int i = blockIdx.x * 1024 + t;
    int m = 0;
    if (i < NG2) {
#pragma unroll
        for (int j = 0; j < ILV; j++) {
            int d = g_cnt[g_order[i * ILV + j]];
            m = d > m ? d : m;
        }
        g_gmax[i] = m;
    }
    sh[t] = m;
    for (int off = 1; off < 1024; off <<= 1) {
        __syncthreads();
        int u = (t >= off) ? sh[t - off] : 0;
        __syncthreads();
        sh[t] += u;
    }
    __syncthreads();
    if (i < NG2) g_gscan[i] = sh[t];
    if (t == 1023) g_gbsum[blockIdx.x] = sh[1023];
}

// fused: top-level scan (13 elems, redundant per block) + gbase + per-node
// slotbase + PRECISE ELL padding (only the slack slots, not all 7M)
__global__ void k_sbpad() {
    __shared__ int boff[NGB2 + 1];
    int t = threadIdx.x;
    if (t == 0) {
        int run = 0;
        for (int j = 0; j < NGB2; j++) { boff[j] = run; run += g_gbsum[j]; }
        boff[NGB2] = run;
    }
    __syncthreads();
    int i = blockIdx.x * 256 + t;
    if (i < NG2) {
        int ex = boff[i >> 10] + g_gscan[i] - g_gmax[i];
        g_gbase[i] = ex * ILV;
    }
    if (i == 0) g_gbase[NG2] = boff[NGB2] * ILV;
    if (i < NN) {
        int r = g_rank[i];
        int g = r >> 4;
        int gm = g_gmax[g];
        int base = (boff[g >> 10] + g_gscan[g] - gm) * ILV;
        int sb = base + (r & 15);
        g_sbc[i].y = sb;
        int deg = g_cnt[i];
        for (int k = deg; k < gm; k++) g_eil[sb + k * ILV] = NN;  // precise pad
    }
}

__global__ void k_scatter2(const int* __restrict__ ei) {
    int e = blockIdx.x * 256 + threadIdx.x;
    if (e < EE) {
        int s = ei[e];
        int d = ei[EE + e];
        int i = atomicAdd(&g_sbc[d].x, 1);
        int sb = g_sbc[d].y;                 // same 8B pair as cursor
        g_eil[sb + i * ILV] = g_rank[s];     // store src RANK
    }
}

// -------- first transform: g_hA[rank(n)] = dis[n] * (x[n] @ w_in) --------
__global__ __launch_bounds__(256) void k_xw(const float* __restrict__ x,
                                            const float* __restrict__ w) {
    __shared__ float xs[16 * 128];
    __shared__ float ws[128 * 16];
    int t = threadIdx.x;
    for (int i = t; i < 2048; i += 256) ws[i] = w[i];
    const float* xb = x + (size_t)blockIdx.x * 2048;
    for (int i = t; i < 2048; i += 256) xs[i] = xb[i];
    __syncthreads();
    int ry = t >> 4, c = t & 15;
    float s = 0.f;
#pragma unroll
    for (int k = 0; k < 128; k++) s = fmaf(xs[ry * 128 + k], ws[k * 16 + c], s);
    int node = blockIdx.x * 16 + ry;
    g_hA[(size_t)g_rank[node] * 16 + c] = __float2half_rn(s * g_dis[node]);
}

// ---------------- cp.async helpers ----------------
__device__ __forceinline__ void cp16(unsigned smem, const void* gptr) {
    asm volatile("cp.async.cg.shared.global [%0], [%1], 16;"
                 :: "r"(smem), "l"(gptr) : "memory");
}
__device__ __forceinline__ void cp_commit() {
    asm volatile("cp.async.commit_group;" ::: "memory");
}
template <int N>
__device__ __forceinline__ void cp_wait() {
    asm volatile("cp.async.wait_group %0;" :: "n"(N) : "memory");
}

__device__ __forceinline__ void h8_init(float* a, uint4 v) {
    __half2* h = (__half2*)&v;
#pragma unroll
    for (int q = 0; q < 4; q++) {
        float2 f = __half22float2(h[q]);
        a[2 * q] = f.x; a[2 * q + 1] = f.y;
    }
}
__device__ __forceinline__ void h8_add(float* a, uint4 v) {
    __half2* h = (__half2*)&v;
#pragma unroll
    for (int q = 0; q < 4; q++) {
        float2 f = __half22float2(h[q]);
        a[2 * q] += f.x; a[2 * q + 1] += f.y;
    }
}
__device__ __forceinline__ uint4 f8_to_h8(const float* a) {
    uint4 r;
    __half2* h = (__half2*)&r;
#pragma unroll
    for (int q = 0; q < 4; q++) h[q] = __floats2half2_rn(a[2 * q], a[2 * q + 1]);
    return r;
}

// ---------------- fused aggregation layers (cp.async gather pipeline) -------
// MODE 0: h = relu(dis*agg+b); store dis*(h @ Wn)    [8x]
// MODE 1: store dis*relu(dis*agg+b)                   [h9]
// MODE 2: o = (dis*agg) @ w_out + b_out; log_softmax  [final]
template <int MODE>
__global__ __launch_bounds__(256) void k_agg(int inA,
                                             const float* __restrict__ preBias,
                                             const float* __restrict__ Wn,
                                             const float* __restrict__ postBias,
                                             float* __restrict__ fout) {
    __shared__ uint4 stage[8][DEPTH][32];
    __shared__ float wsh[640];
    __shared__ float bsh[40];
    __shared__ float hsh[128 * 17];
    int t = threadIdx.x;
    if (MODE == 0) wsh[t] = Wn[t & 255];
    if (MODE == 2) {
        for (int i = t; i < 640; i += 256) wsh[i] = Wn[i];
        if (t < 40) bsh[t] = postBias[t];
    }
    __syncthreads();

    int w = t >> 5, lane = t & 31;
    int gw = blockIdx.x * 8 + w;
    if (gw >= NG2) return;

    const uint4* tab = (const uint4*)(inA ? g_hA : g_hB);
    __half* outF = inA ? g_hB : g_hA;

    int j = lane >> 1, h = lane & 1;
    int row = gw * ILV + j;            // rank-ordered feature row
    float di = g_disP[row];

    float acc[8];
    h8_init(acc, __ldg(&tab[row * 2 + h]));   // self loop (coalesced)

    int base = g_gbase[gw];
    int nch = (g_gbase[gw + 1] - base) >> 4;
    const int* eilc = g_eil + base + j;
    unsigned sa0 = (unsigned)__cvta_generic_to_shared(&stage[w][0][lane]);

    int npro = nch < DEPTH ? nch : DEPTH;
    for (int c = 0; c < npro; c++) {
        int src = __ldg(eilc + c * ILV);
        cp16(sa0 + (c & (DEPTH - 1)) * 512, tab + src * 2 + h);
        cp_commit();
    }
    int c = 0;
    for (; c + DEPTH < nch; c++) {
        cp_wait<DEPTH - 1>();                       // buf c ready
        h8_add(acc, stage[w][c & (DEPTH - 1)][lane]);
        int cn = c + DEPTH;
        int src = __ldg(eilc + cn * ILV);
        cp16(sa0 + (cn & (DEPTH - 1)) * 512, tab + src * 2 + h);
        cp_commit();
    }
    cp_wait<0>();
    for (; c < nch; c++) h8_add(acc, stage[w][c & (DEPTH - 1)][lane]);

#pragma unroll
    for (int q = 0; q < 8; q++) acc[q] *= di;

    if (MODE != 2) {  // bias + relu
        const float* bp = preBias + h * 8;
#pragma unroll
        for (int q = 0; q < 8; q++) acc[q] = fmaxf(acc[q] + __ldg(bp + q), 0.f);
    }

    if (MODE == 1) {  // store dis*h (coalesced, rank order)
#pragma unroll
        for (int q = 0; q < 8; q++) acc[q] *= di;
        ((uint4*)outF)[row * 2 + h] = f8_to_h8(acc);
        return;
    }

    // share the node's 16-vector between its 2 lanes
    float* hr = &hsh[(t >> 1) * 17];
#pragma unroll
    for (int q = 0; q < 8; q++) hr[h * 8 + q] = acc[q];
    __syncwarp();

    if (MODE == 0) {  // 16x16 transform, store pre-scaled by dis
        float o[8];
#pragma unroll
        for (int jj = 0; jj < 8; jj++) {
            int col = h * 8 + jj;
            float s = 0.f;
#pragma unroll
            for (int k = 0; k < 16; k++) s = fmaf(hr[k], wsh[k * 16 + col], s);
            o[jj] = s * di;
        }
        ((uint4*)outF)[row * 2 + h] = f8_to_h8(o);
    } else {  // MODE 2: 16x40 output transform + log_softmax
        float o[20];
#pragma unroll
        for (int jj = 0; jj < 20; jj++) {
            int col = h * 20 + jj;
            float s = bsh[col];
#pragma unroll
            for (int k = 0; k < 16; k++) s = fmaf(hr[k], wsh[k * 40 + col], s);
            o[jj] = s;
        }
        float m = o[0];
#pragma unroll
        for (int jj = 1; jj < 20; jj++) m = fmaxf(m, o[jj]);
        m = fmaxf(m, __shfl_xor_sync(0xffffffffu, m, 1));
        float se = 0.f;
#pragma unroll
        for (int jj = 0; jj < 20; jj++) se += __expf(o[jj] - m);
        se += __shfl_xor_sync(0xffffffffu, se, 1);
        float l = m + __logf(se);
        int node = g_order[row];
#pragma unroll
        for (int jj = 0; jj < 20; jj++)
            fout[(size_t)node * 40 + h * 20 + jj] = o[jj] - l;
    }
}

// ---------------- launch ----------------
extern "C" void kernel_launch(void* const* d_in, const int* in_sizes, int n_in,
                              void* d_out, int out_size) {
    const float* x     = (const float*)d_in[0];
    const float* w_in  = (const float*)d_in[1];
    const float* b_in  = (const float*)d_in[2];
    const float* w_hid = (const float*)d_in[3];
    const float* b_hid = (const float*)d_in[4];
    const float* w_out = (const float*)d_in[5];
    const float* b_out = (const float*)d_in[6];
    const int*   ei    = (const int*)d_in[7];
    float* out = (float*)d_out;

    const int NB_N = (NN + 255) / 256;    // 782
    const int NB_E = EE / 256;            // 25000
    const int NB_A = (NG2 + 7) / 8;       // 1563

    // prep: counts -> degree sort -> group bases (+precise pad) -> ELL scatter
    k_zero<<<NB_N, 256>>>();
    k_hist<<<NB_E, 256>>>(ei);
    k_dhist<<<NB_N, 256>>>();
    k_dscan<<<1, NBIN>>>();
    k_dplace<<<NB_N, 256>>>();
    k_gmaxscan<<<NGB2, 1024>>>();
    k_sbpad<<<NB_N, 256>>>();
    k_scatter2<<<NB_E, 256>>>(ei);

    // t0-hat = dis * (x @ w_in)  -> g_hA (rank order)
    k_xw<<<NN / 16, 256>>>(x, w_in);

    // layers 1..8: fused agg + bias + relu + next 16x16 transform (ping-pong)
    k_agg<0><<<NB_A, 256>>>(1, b_in,         w_hid + 0 * 256, nullptr, nullptr);
    k_agg<0><<<NB_A, 256>>>(0, b_hid + 0*16, w_hid + 1 * 256, nullptr, nullptr);
    k_agg<0><<<NB_A, 256>>>(1, b_hid + 1*16, w_hid + 2 * 256, nullptr, nullptr);
    k_agg<0><<<NB_A, 256>>>(0, b_hid + 2*16, w_hid + 3 * 256, nullptr, nullptr);
    k_agg<0><<<NB_A, 256>>>(1, b_hid + 3*16, w_hid + 4 * 256, nullptr, nullptr);
    k_agg<0><<<NB_A, 256>>>(0, b_hid + 4*16, w_hid + 5 * 256, nullptr, nullptr);
    k_agg<0><<<NB_A, 256>>>(1, b_hid + 5*16, w_hid + 6 * 256, nullptr, nullptr);
    k_agg<0><<<NB_A, 256>>>(0, b_hid + 6*16, w_hid + 7 * 256, nullptr, nullptr);
    // layer 9: h9-hat (hA -> hB)
    k_agg<1><<<NB_A, 256>>>(1, b_hid + 7*16, nullptr, nullptr, nullptr);
    // layer 10: out = log_softmax((dis*agg(h9-hat)) @ w_out + b_out)
    k_agg<2><<<NB_A, 256>>>(0, nullptr, w_out, b_out, out);
}